// round 13
// baseline (speedup 1.0000x reference)
#include <cuda_runtime.h>
#include <cuda_fp16.h>
#include <cstdint>

// ---------------- problem constants ----------------
#define B_   2
#define T_   1024
#define DM   1024      // d_model
#define DI   2048      // d_inner
#define DS   16        // d_state
#define TOK  (B_ * T_) // 2048 tokens
#define NCH  32        // scan chunks
#define CHL  32        // chunk length
#define KSL  8         // bc split-K slices

// ---------------- scratch (static device memory) ----------------
__device__ __half g_xnh  [TOK * DM];
__device__ __half g_WinH [DM * 2 * DI];
__device__ __half g_WoutH[DI * DM];
__device__ __half g_WBC  [DI * 32];
__device__ __half g_projh[TOK * 2 * DI];
__device__ __half g_xch  [TOK * DI];
__device__ float  g_Bt   [TOK * DS];
__device__ float  g_Ct   [TOK * DS];
__device__ float  g_E    [B_ * NCH * DI * DS];
__device__ float  g_S    [B_ * NCH * DI * DS];
__device__ __half g_y    [TOK * DI];
__device__ float  g_BCp  [KSL][TOK][32];
__device__ float  g_G2p  [2][TOK * DM];
__device__ int    g_cntG2[128];              // gemm2 tile counters (8 x 16)
__device__ int    g_cntBC[16];               // bc tile counters

__device__ __forceinline__ float sigmoidf_(float x) { return 1.0f / (1.0f + __expf(-x)); }
__device__ __forceinline__ float siluf_(float x)    { return x / (1.0f + __expf(-x)); }

__device__ __forceinline__ uint32_t smem_u32(const void* p) {
    uint32_t a;
    asm("{ .reg .u64 t; cvta.to.shared.u64 t, %1; cvt.u32.u64 %0, t; }"
        : "=r"(a) : "l"(p));
    return a;
}
__device__ __forceinline__ void cp16(uint32_t dst, const void* src) {
    asm volatile("cp.async.cg.shared.global [%0], [%1], 16;"
                 :: "r"(dst), "l"(src) : "memory");
}
__device__ __forceinline__ void ldsm4(uint32_t* r, uint32_t addr) {
    asm volatile("ldmatrix.sync.aligned.m8n8.x4.shared.b16 {%0,%1,%2,%3}, [%4];"
        : "=r"(r[0]), "=r"(r[1]), "=r"(r[2]), "=r"(r[3]) : "r"(addr));
}
__device__ __forceinline__ void ldsm4t(uint32_t* r, uint32_t addr) {
    asm volatile("ldmatrix.sync.aligned.m8n8.x4.trans.shared.b16 {%0,%1,%2,%3}, [%4];"
        : "=r"(r[0]), "=r"(r[1]), "=r"(r[2]), "=r"(r[3]) : "r"(addr));
}
__device__ __forceinline__ void mma_f16(float* c, const uint32_t* a, const uint32_t* b) {
    asm volatile(
        "mma.sync.aligned.m16n8k16.row.col.f32.f16.f16.f32 "
        "{%0,%1,%2,%3}, {%4,%5,%6,%7}, {%8,%9}, {%0,%1,%2,%3};"
        : "+f"(c[0]), "+f"(c[1]), "+f"(c[2]), "+f"(c[3])
        : "r"(a[0]), "r"(a[1]), "r"(a[2]), "r"(a[3]), "r"(b[0]), "r"(b[1]));
}

// ---------------- 1. fused prep: zero-cnts | f2h(W_in) | f2h(W_out) | pack_wbc | LN ----------------
#define PREP_Z_BLKS    1
#define PREP_WIN_BLKS  ((DM * 2 * DI) / 1024)   // 4096
#define PREP_WOUT_BLKS ((DI * DM) / 1024)       // 2048
#define PREP_WBC_BLKS  ((DI * 32) / 256)        // 256
#define PREP_LN_BLKS   TOK                      // 2048
#define PREP_BLKS (PREP_Z_BLKS + PREP_WIN_BLKS + PREP_WOUT_BLKS + PREP_WBC_BLKS + PREP_LN_BLKS)

__global__ void prep_kernel(const float* __restrict__ x,
                            const float* __restrict__ ln_g,
                            const float* __restrict__ ln_b,
                            const float* __restrict__ W_in,
                            const float* __restrict__ W_out,
                            const float* __restrict__ WB,
                            const float* __restrict__ WC) {
    __shared__ float ss[8], sq[8];
    __shared__ float smu, srstd;
    int blk = blockIdx.x;
    int tid = threadIdx.x;

    if (blk < PREP_Z_BLKS) {                        // reset split-K counters
        if (tid < 128) g_cntG2[tid] = 0;
        if (tid < 16)  g_cntBC[tid] = 0;
        return;
    }
    blk -= PREP_Z_BLKS;
    if (blk < PREP_WIN_BLKS) {
        int i = blk * 256 + tid;
        float4 v = ((const float4*)W_in)[i];
        ((__half2*)g_WinH)[i * 2]     = __floats2half2_rn(v.x, v.y);
        ((__half2*)g_WinH)[i * 2 + 1] = __floats2half2_rn(v.z, v.w);
        return;
    }
    blk -= PREP_WIN_BLKS;
    if (blk < PREP_WOUT_BLKS) {
        int i = blk * 256 + tid;
        float4 v = ((const float4*)W_out)[i];
        ((__half2*)g_WoutH)[i * 2]     = __floats2half2_rn(v.x, v.y);
        ((__half2*)g_WoutH)[i * 2 + 1] = __floats2half2_rn(v.z, v.w);
        return;
    }
    blk -= PREP_WOUT_BLKS;
    if (blk < PREP_WBC_BLKS) {
        int i = blk * 256 + tid;
        int k = i >> 5, o = i & 31;
        float v = (o < 16) ? WB[k * DS + o] : WC[k * DS + (o - 16)];
        g_WBC[i] = __float2half(v);
        return;
    }
    blk -= PREP_WBC_BLKS;
    {
        int row = blk;
        const float4* xr = (const float4*)(x + (size_t)row * DM);
        float4 v = xr[tid];
        float s = v.x + v.y + v.z + v.w;
        float q = v.x * v.x + v.y * v.y + v.z * v.z + v.w * v.w;
        #pragma unroll
        for (int o = 16; o; o >>= 1) {
            s += __shfl_down_sync(0xFFFFFFFFu, s, o);
            q += __shfl_down_sync(0xFFFFFFFFu, q, o);
        }
        int w = tid >> 5, l = tid & 31;
        if (l == 0) { ss[w] = s; sq[w] = q; }
        __syncthreads();
        if (tid == 0) {
            float S = 0.f, Q = 0.f;
            #pragma unroll
            for (int i = 0; i < 8; i++) { S += ss[i]; Q += sq[i]; }
            float mu = S * (1.0f / DM);
            float var = Q * (1.0f / DM) - mu * mu;
            smu = mu; srstd = rsqrtf(var + 1e-5f);
        }
        __syncthreads();
        float mu = smu, rstd = srstd;
        float4 gv = ((const float4*)ln_g)[tid];
        float4 bv = ((const float4*)ln_b)[tid];
        __half2* orow = (__half2*)(g_xnh + (size_t)row * DM);
        orow[tid * 2]     = __floats2half2_rn((v.x - mu) * rstd * gv.x + bv.x,
                                              (v.y - mu) * rstd * gv.y + bv.y);
        orow[tid * 2 + 1] = __floats2half2_rn((v.z - mu) * rstd * gv.z + bv.z,
                                              (v.w - mu) * rstd * gv.w + bv.w);
    }
}

// ---------------- fp16 mma GEMM, 4-stage, hoisted frags, no bottom sync ----------------
// MODE 0: C = A@B + bias.  MODE 2: split-K2 with in-kernel last-CTA reduce:
//   partials to Cmat (=g_G2p), last CTA of each tile writes finalOut = p0+p1+bias+resid.
#define GA_ST 80
#define GA_BYTES (128 * GA_ST)
#define GB_ST 272
#define GB_BYTES (32 * GB_ST)
#define GSTAGE (GA_BYTES + GB_BYTES)
#define GSM (4 * GSTAGE)

template <int MODE, typename OutT>
__global__ __launch_bounds__(256, 2) void gemm_f16(
    const __half* __restrict__ Amat, const __half* __restrict__ Bmat,
    const float* __restrict__ bias, const float* __restrict__ resid,
    OutT* __restrict__ Cmat, float* __restrict__ finalOut, int M, int N, int K)
{
    extern __shared__ char sm[];
    uint32_t sb = smem_u32(sm);
    int tid = threadIdx.x;
    int wid = tid >> 5, lane = tid & 31;
    int wm = wid >> 2, wn = wid & 3;
    int gid = lane >> 2, tig = lane & 3;
    int mBase = blockIdx.y * 128, nBase = blockIdx.x * 128;
    int kOff = (MODE == 2) ? blockIdx.z * (K / 2) : 0;
    const int S = (MODE == 2) ? (K / 2) / 32 : K / 32;
    OutT* Cout = (MODE == 2) ? Cmat + (size_t)blockIdx.z * M * N : Cmat;

    float acc[4][4][4];
    #pragma unroll
    for (int i = 0; i < 4; i++)
        #pragma unroll
        for (int j = 0; j < 4; j++)
            #pragma unroll
            for (int c = 0; c < 4; c++) acc[i][j][c] = 0.f;

    auto stage_load = [&](int buf, int k0) {
        uint32_t ab = sb + buf * GSTAGE;
        uint32_t bb = ab + GA_BYTES;
        #pragma unroll
        for (int q = 0; q < 2; q++) {
            int lin = tid + q * 256;
            int row = lin >> 2, ch = lin & 3;
            cp16(ab + row * GA_ST + ch * 16,
                 Amat + (size_t)(mBase + row) * K + k0 + ch * 8);
        }
        #pragma unroll
        for (int q = 0; q < 2; q++) {
            int lin = tid + q * 256;
            int row = lin >> 4, ch = lin & 15;
            cp16(bb + row * GB_ST + ch * 16,
                 Bmat + (size_t)(k0 + row) * N + nBase + ch * 8);
        }
        asm volatile("cp.async.commit_group;" ::: "memory");
    };

    stage_load(0, kOff);
    stage_load(1, kOff + 32);
    stage_load(2, kOff + 64);
    for (int s = 0; s < S; s++) {
        asm volatile("cp.async.wait_group 2;" ::: "memory");
        __syncthreads();
        if (s + 3 < S) stage_load((s + 3) & 3, kOff + (s + 3) * 32);
        else           asm volatile("cp.async.commit_group;" ::: "memory");

        uint32_t ab = sb + (s & 3) * GSTAGE;
        uint32_t bb = ab + GA_BYTES;
        uint32_t af[2][4][4], bf[2][2][4];
        #pragma unroll
        for (int k16 = 0; k16 < 2; k16++) {
            #pragma unroll
            for (int mt = 0; mt < 4; mt++) {
                uint32_t addr = ab + (wm * 64 + mt * 16 + (lane & 15)) * GA_ST
                              + k16 * 32 + ((lane >> 4) << 4);
                ldsm4(af[k16][mt], addr);
            }
            #pragma unroll
            for (int bt = 0; bt < 2; bt++) {
                uint32_t addr = bb + (k16 * 16 + (lane & 15)) * GB_ST
                              + (wn * 32 + bt * 16 + ((lane >> 4) << 3)) * 2;
                ldsm4t(bf[k16][bt], addr);
            }
        }
        #pragma unroll
        for (int k16 = 0; k16 < 2; k16++)
            #pragma unroll
            for (int mt = 0; mt < 4; mt++)
                #pragma unroll
                for (int nt = 0; nt < 4; nt++)
                    mma_f16(acc[mt][nt], af[k16][mt], &bf[k16][nt >> 1][(nt & 1) * 2]);
    }

    #pragma unroll
    for (int mt = 0; mt < 4; mt++) {
        int r0 = mBase + wm * 64 + mt * 16 + gid;
        #pragma unroll
        for (int nt = 0; nt < 4; nt++) {
            int cN = nBase + wn * 32 + nt * 8 + tig * 2;
            float o0x = acc[mt][nt][0], o0y = acc[mt][nt][1];
            float o1x = acc[mt][nt][2], o1y = acc[mt][nt][3];
            if (MODE == 0) {
                float2 bv = *(const float2*)(bias + cN);
                o0x += bv.x; o0y += bv.y;
                o1x += bv.x; o1y += bv.y;
            }
            if (sizeof(OutT) == 2) {
                *(__half2*)((__half*)Cout + (size_t)r0 * N + cN)       = __floats2half2_rn(o0x, o0y);
                *(__half2*)((__half*)Cout + (size_t)(r0 + 8) * N + cN) = __floats2half2_rn(o1x, o1y);
            } else {
                *(float2*)((float*)Cout + (size_t)r0 * N + cN)       = make_float2(o0x, o0y);
                *(float2*)((float*)Cout + (size_t)(r0 + 8) * N + cN) = make_float2(o1x, o1y);
            }
        }
    }

    if (MODE == 2) {
        // last CTA of the tile reduces p0+p1+bias+resid -> finalOut
        __shared__ int sflag;
        __syncthreads();
        if (tid == 0) {
            __threadfence();
            int old = atomicAdd(&g_cntG2[blockIdx.y * gridDim.x + blockIdx.x], 1);
            sflag = (old == 1);
        }
        __syncthreads();
        if (sflag) {
            const float* P = (const float*)Cmat;
            for (int e = tid; e < (128 * 128) / 4; e += 256) {
                int r = e >> 5, c4 = e & 31;
                size_t off = (size_t)(mBase + r) * N + nBase + c4 * 4;
                float4 p0 = *(const float4*)(P + off);
                float4 p1 = *(const float4*)(P + (size_t)M * N + off);
                float4 bv = *(const float4*)(bias + nBase + c4 * 4);
                float4 xv = *(const float4*)(resid + off);
                float4 o;
                o.x = p0.x + p1.x + bv.x + xv.x;
                o.y = p0.y + p1.y + bv.y + xv.y;
                o.z = p0.z + p1.z + bv.z + xv.z;
                o.w = p0.w + p1.w + bv.w + xv.w;
                *(float4*)(finalOut + off) = o;
            }
        }
    }
}

// ---------------- 3. depthwise causal conv1d + silu (half2, 2 ch/thread) ----------------
__global__ void conv_silu_kernel(const float* __restrict__ cw,
                                 const float* __restrict__ cb) {
    int i = blockIdx.x * 256 + threadIdx.x;     // over TOK*DI/2
    int d2  = i & (DI / 2 - 1);
    int d   = d2 * 2;
    int tok = i >> 10;                          // DI/2 = 1024
    int t   = tok & (T_ - 1);
    float4 w0 = *(const float4*)(cw + d * 4);
    float4 w1 = *(const float4*)(cw + d * 4 + 4);
    float2 cbv = *(const float2*)(cb + d);
    const __half* base = g_projh + (size_t)tok * (2 * DI) + d;
    float a0 = cbv.x, a1 = cbv.y;
    if (t >= 3) { __half2 v = *(const __half2*)(base - 3 * 2 * DI);
                  float2 f = __half22float2(v); a0 = fmaf(w0.x, f.x, a0); a1 = fmaf(w1.x, f.y, a1); }
    if (t >= 2) { __half2 v = *(const __half2*)(base - 2 * 2 * DI);
                  float2 f = __half22float2(v); a0 = fmaf(w0.y, f.x, a0); a1 = fmaf(w1.y, f.y, a1); }
    if (t >= 1) { __half2 v = *(const __half2*)(base - 1 * 2 * DI);
                  float2 f = __half22float2(v); a0 = fmaf(w0.z, f.x, a0); a1 = fmaf(w1.z, f.y, a1); }
    { __half2 v = *(const __half2*)(base);
      float2 f = __half22float2(v); a0 = fmaf(w0.w, f.x, a0); a1 = fmaf(w1.w, f.y, a1); }
    *(__half2*)(g_xch + (size_t)tok * DI + d) = __floats2half2_rn(siluf_(a0), siluf_(a1));
}

// ---------------- 4. B_t / C_t: fp16 mma split-K GEMM with in-kernel reduce ----------------
#define CA_BYTES (128 * 80)
#define CB_BYTES (32 * 80)
#define CSTAGE (CA_BYTES + CB_BYTES)
#define CSM (3 * CSTAGE)

__global__ __launch_bounds__(256) void bc_mma_kernel(const float* __restrict__ bB,
                                                     const float* __restrict__ bC) {
    extern __shared__ char sm[];
    uint32_t sb = smem_u32(sm);
    int tid = threadIdx.x;
    int wid = tid >> 5, lane = tid & 31;
    int wm = wid >> 1, wn = wid & 1;
    int gid = lane >> 2, tig = lane & 3;
    int tok0 = blockIdx.x * 128;
    int kBase = blockIdx.y * (DI / KSL);
    const __half* X = g_xch;
    const __half* W = g_WBC;

    float acc[2][2][4];
    #pragma unroll
    for (int i = 0; i < 2; i++)
        #pragma unroll
        for (int j = 0; j < 2; j++)
            #pragma unroll
            for (int c = 0; c < 4; c++) acc[i][j][c] = 0.f;

    auto stage_load = [&](int buf, int k0) {
        uint32_t ab = sb + buf * CSTAGE;
        uint32_t bb = ab + CA_BYTES;
        #pragma unroll
        for (int q = 0; q < 2; q++) {
            int lin = tid + q * 256;
            int row = lin >> 2, ch = lin & 3;
            cp16(ab + row * 80 + ch * 16,
                 X + (size_t)(tok0 + row) * DI + kBase + k0 + ch * 8);
        }
        if (tid < 128) {
            int row = tid >> 2, ch = tid & 3;
            cp16(bb + row * 80 + ch * 16,
                 W + (size_t)(kBase + k0 + row) * 32 + ch * 8);
        }
        asm volatile("cp.async.commit_group;" ::: "memory");
    };

    const int S = (DI / KSL) / 32;
    stage_load(0, 0);
    stage_load(1, 32);
    for (int s = 0; s < S; s++) {
        asm volatile("cp.async.wait_group 1;" ::: "memory");
        __syncthreads();
        if (s + 2 < S) stage_load((s + 2) % 3, (s + 2) * 32);

        uint32_t ab = sb + (s % 3) * CSTAGE;
        uint32_t bb = ab + CA_BYTES;
        uint32_t af[2][2][4], bf[2][4];
        #pragma unroll
        for (int k16 = 0; k16 < 2; k16++) {
            #pragma unroll
            for (int mt = 0; mt < 2; mt++) {
                uint32_t addr = ab + (wm * 32 + mt * 16 + (lane & 15)) * 80
                              + k16 * 32 + ((lane >> 4) << 4);
                ldsm4(af[k16][mt], addr);
            }
            {
                uint32_t addr = bb + (k16 * 16 + (lane & 15)) * 80
                              + (wn * 16 + ((lane >> 4) << 3)) * 2;
                ldsm4t(bf[k16], addr);
            }
        }
        #pragma unroll
        for (int k16 = 0; k16 < 2; k16++)
            #pragma unroll
            for (int mt = 0; mt < 2; mt++)
                #pragma unroll
                for (int nt = 0; nt < 2; nt++)
                    mma_f16(acc[mt][nt], af[k16][mt], &bf[k16][nt * 2]);
    }

    #pragma unroll
    for (int mt = 0; mt < 2; mt++) {
        int r0 = tok0 + wm * 32 + mt * 16 + gid;
        #pragma unroll
        for (int nt = 0; nt < 2; nt++) {
            int o = wn * 16 + nt * 8 + tig * 2;
            *(float2*)&g_BCp[blockIdx.y][r0][o]     = make_float2(acc[mt][nt][0], acc[mt][nt][1]);
            *(float2*)&g_BCp[blockIdx.y][r0 + 8][o] = make_float2(acc[mt][nt][2], acc[mt][nt][3]);
        }
    }

    // last K-slice CTA for this token block reduces all 8 partials
    __shared__ int sflag;
    __syncthreads();
    if (tid == 0) {
        __threadfence();
        int old = atomicAdd(&g_cntBC[blockIdx.x], 1);
        sflag = (old == KSL - 1);
    }
    __syncthreads();
    if (sflag) {
        for (int e = tid; e < 128 * 32; e += 256) {
            int r = e >> 5, o = e & 31;
            float s = 0.f;
            #pragma unroll
            for (int p = 0; p < KSL; p++) s += g_BCp[p][tok0 + r][o];
            if (o < 16) g_Bt[(tok0 + r) * DS + o]        = s + bB[o];
            else        g_Ct[(tok0 + r) * DS + (o - 16)] = s + bC[o - 16];
        }
    }
}

// ---------------- 5. scan pass 1 ----------------
__global__ void scan1_kernel(const float* __restrict__ A) {
    __shared__ float sB[CHL][DS];
    int tid = threadIdx.x;
    int d  = blockIdx.x * 128 + tid;
    int ch = blockIdx.y, bb = blockIdx.z;
    int tok0 = bb * T_ + ch * CHL;
    float* sBf = &sB[0][0];
    #pragma unroll
    for (int q = 0; q < (CHL * DS) / 128; q++)
        sBf[tid + q * 128] = g_Bt[tok0 * DS + tid + q * 128];
    float a[DS], h[DS];
    #pragma unroll
    for (int s = 0; s < DS; s++) {
        a[s] = sigmoidf_(A[d * DS + s]);
        h[s] = 0.f;
    }
    __syncthreads();
    for (int t = 0; t < CHL; t++) {
        float x = __half2float(g_xch[(size_t)(tok0 + t) * DI + d]);
        #pragma unroll
        for (int s = 0; s < DS; s++)
            h[s] = fmaf(a[s], h[s], sB[t][s] * x);
    }
    float* ep = g_E + ((size_t)(bb * NCH + ch) * DI + d) * DS;
    #pragma unroll
    for (int s = 0; s < DS; s++) ep[s] = h[s];
}

// ---------------- 6. serial carry ----------------
__global__ void carry_kernel(const float* __restrict__ A) {
    int idx = blockIdx.x * 256 + threadIdx.x;
    int d = idx & (DI - 1), bb = idx >> 11;
    float aL[DS], st[DS];
    #pragma unroll
    for (int s = 0; s < DS; s++) {
        float a = sigmoidf_(A[d * DS + s]);
        #pragma unroll
        for (int r = 0; r < 5; r++) a *= a;   // a^32
        aL[s] = a;
        st[s] = 0.f;
    }
    for (int c = 0; c < NCH; c++) {
        float* sp = g_S + ((size_t)(bb * NCH + c) * DI + d) * DS;
        const float* ep = g_E + ((size_t)(bb * NCH + c) * DI + d) * DS;
        #pragma unroll
        for (int s = 0; s < DS; s++) sp[s] = st[s];
        #pragma unroll
        for (int s = 0; s < DS; s++) st[s] = fmaf(aL[s], st[s], ep[s]);
    }
}

// ---------------- 7. scan pass 2 + gate epilogue ----------------
__global__ void scan2_kernel(const float* __restrict__ A,
                             const float* __restrict__ Dv) {
    __shared__ float sB[CHL][DS], sC[CHL][DS];
    int tid = threadIdx.x;
    int d  = blockIdx.x * 128 + tid;
    int ch = blockIdx.y, bb = blockIdx.z;
    int tok0 = bb * T_ + ch * CHL;
    #pragma unroll
    for (int q = 0; q < (CHL * DS) / 128; q++) {
        (&sB[0][0])[tid + q * 128] = g_Bt[tok0 * DS + tid + q * 128];
        (&sC[0][0])[tid + q * 128] = g_Ct[tok0 * DS + tid + q * 128];
    }
    const float* sp = g_S + ((size_t)(bb * NCH + ch) * DI + d) * DS;
    float a[DS], h[DS];
    #pragma unroll
    for (int s = 0; s < DS; s++) {
        a[s] = sigmoidf_(A[d * DS + s]);
        h[s] = sp[s];
    }
    float Dd = Dv[d];
    __syncthreads();
    for (int t = 0; t < CHL; t++) {
        int tok = tok0 + t;
        float x = __half2float(g_xch[(size_t)tok * DI + d]);
        float yv = Dd * x;
        #pragma unroll
        for (int s = 0; s < DS; s++) {
            h[s] = fmaf(a[s], h[s], sB[t][s] * x);
            yv = fmaf(h[s], sC[t][s], yv);
        }
        float gt = __half2float(g_projh[(size_t)tok * (2 * DI) + DI + d]);
        g_y[(size_t)tok * DI + d] = __float2half(yv * siluf_(gt));
    }
}

// ---------------- launch ----------------
extern "C" void kernel_launch(void* const* d_in, const int* in_sizes, int n_in,
                              void* d_out, int out_size) {
    const float* x      = (const float*)d_in[0];
    const float* ln_g   = (const float*)d_in[1];
    const float* ln_b   = (const float*)d_in[2];
    const float* W_in   = (const float*)d_in[3];
    const float* b_in   = (const float*)d_in[4];
    const float* conv_w = (const float*)d_in[5];
    const float* conv_b = (const float*)d_in[6];
    const float* A      = (const float*)d_in[7];
    const float* W_B    = (const float*)d_in[8];
    const float* b_B    = (const float*)d_in[9];
    const float* W_C    = (const float*)d_in[10];
    const float* b_C    = (const float*)d_in[11];
    const float* Dv     = (const float*)d_in[12];
    const float* W_out  = (const float*)d_in[13];
    const float* b_out  = (const float*)d_in[14];
    float* out = (float*)d_out;

    void *pxnh, *pprojh, *py, *pwih, *pwoh, *pg2p;
    cudaGetSymbolAddress(&pxnh,  g_xnh);
    cudaGetSymbolAddress(&pprojh, g_projh);
    cudaGetSymbolAddress(&py,    g_y);
    cudaGetSymbolAddress(&pwih,  g_WinH);
    cudaGetSymbolAddress(&pwoh,  g_WoutH);
    cudaGetSymbolAddress(&pg2p,  g_G2p);

    cudaFuncSetAttribute((const void*)gemm_f16<0, __half>,
                         cudaFuncAttributeMaxDynamicSharedMemorySize, GSM);
    cudaFuncSetAttribute((const void*)gemm_f16<2, float>,
                         cudaFuncAttributeMaxDynamicSharedMemorySize, GSM);
    cudaFuncSetAttribute((const void*)bc_mma_kernel,
                         cudaFuncAttributeMaxDynamicSharedMemorySize, CSM);

    // 1. fused prep (zero counters + ln + weight converts + wbc pack)
    prep_kernel<<<PREP_BLKS, 256>>>(x, ln_g, ln_b, W_in, W_out, W_B, W_C);

    // 2. proj = xn @ W_in + b_in   (M=2048, N=4096, K=1024)
    gemm_f16<0, __half><<<dim3((2 * DI) / 128, TOK / 128), 256, GSM>>>(
        (const __half*)pxnh, (const __half*)pwih, b_in, x /*unused*/,
        (__half*)pprojh, nullptr, TOK, 2 * DI, DM);

    // 3.
    conv_silu_kernel<<<(TOK * DI) / 512, 256>>>(conv_w, conv_b);

    // 4. bc partials + fused reduce (profiled slot)
    bc_mma_kernel<<<dim3(TOK / 128, KSL), 256, CSM>>>(b_B, b_C);

    // 5-7.
    scan1_kernel<<<dim3(DI / 128, NCH, B_), 128>>>(A);
    carry_kernel<<<(B_ * DI) / 256, 256>>>(A);
    scan2_kernel<<<dim3(DI / 128, NCH, B_), 128>>>(A, Dv);

    // 8. gemm2 split-K2 + fused last-CTA reduce -> out
    gemm_f16<2, float><<<dim3(DM / 128, TOK / 128, 2), 256, GSM>>>(
        (const __half*)py, (const __half*)pwoh, b_out, x,
        (float*)pg2p, out, TOK, DM, DI);
}

// round 15
// speedup vs baseline: 1.0420x; 1.0420x over previous
#include <cuda_runtime.h>
#include <cuda_fp16.h>
#include <cstdint>

// ---------------- problem constants ----------------
#define B_   2
#define T_   1024
#define DM   1024      // d_model
#define DI   2048      // d_inner
#define DS   16        // d_state
#define TOK  (B_ * T_) // 2048 tokens
#define NCH  32        // scan chunks
#define CHL  32        // chunk length
#define KSL  8         // bc split-K slices

// ---------------- scratch (static device memory) ----------------
__device__ __half g_xnh  [TOK * DM];
__device__ __half g_WinH [DM * 2 * DI];
__device__ __half g_WoutH[DI * DM];
__device__ __half g_WBC  [DI * 32];
__device__ __half g_projh[TOK * 2 * DI];
__device__ __half g_xch  [TOK * DI];
__device__ float  g_Bt   [TOK * DS];
__device__ float  g_Ct   [TOK * DS];
__device__ float  g_E    [B_ * NCH * DI * DS];
__device__ float  g_S    [B_ * NCH * DI * DS];
__device__ __half g_y    [TOK * DI];
__device__ float  g_BCp  [KSL][TOK][32];
__device__ float  g_G2p  [2][TOK * DM];

__device__ __forceinline__ float sigmoidf_(float x) { return 1.0f / (1.0f + __expf(-x)); }
__device__ __forceinline__ float siluf_(float x)    { return x / (1.0f + __expf(-x)); }

__device__ __forceinline__ uint32_t smem_u32(const void* p) {
    uint32_t a;
    asm("{ .reg .u64 t; cvta.to.shared.u64 t, %1; cvt.u32.u64 %0, t; }"
        : "=r"(a) : "l"(p));
    return a;
}
__device__ __forceinline__ void cp16(uint32_t dst, const void* src) {
    asm volatile("cp.async.cg.shared.global [%0], [%1], 16;"
                 :: "r"(dst), "l"(src) : "memory");
}
__device__ __forceinline__ void ldsm4(uint32_t* r, uint32_t addr) {
    asm volatile("ldmatrix.sync.aligned.m8n8.x4.shared.b16 {%0,%1,%2,%3}, [%4];"
        : "=r"(r[0]), "=r"(r[1]), "=r"(r[2]), "=r"(r[3]) : "r"(addr));
}
__device__ __forceinline__ void ldsm4t(uint32_t* r, uint32_t addr) {
    asm volatile("ldmatrix.sync.aligned.m8n8.x4.trans.shared.b16 {%0,%1,%2,%3}, [%4];"
        : "=r"(r[0]), "=r"(r[1]), "=r"(r[2]), "=r"(r[3]) : "r"(addr));
}
__device__ __forceinline__ void mma_f16(float* c, const uint32_t* a, const uint32_t* b) {
    asm volatile(
        "mma.sync.aligned.m16n8k16.row.col.f32.f16.f16.f32 "
        "{%0,%1,%2,%3}, {%4,%5,%6,%7}, {%8,%9}, {%0,%1,%2,%3};"
        : "+f"(c[0]), "+f"(c[1]), "+f"(c[2]), "+f"(c[3])
        : "r"(a[0]), "r"(a[1]), "r"(a[2]), "r"(a[3]), "r"(b[0]), "r"(b[1]));
}

// ---------------- 1. fused prep: f2h(W_in) | f2h(W_out) | pack_wbc | LayerNorm ----------------
#define PREP_WIN_BLKS  ((DM * 2 * DI) / 1024)   // 4096
#define PREP_WOUT_BLKS ((DI * DM) / 1024)       // 2048
#define PREP_WBC_BLKS  ((DI * 32) / 256)        // 256
#define PREP_LN_BLKS   TOK                      // 2048
#define PREP_BLKS (PREP_WIN_BLKS + PREP_WOUT_BLKS + PREP_WBC_BLKS + PREP_LN_BLKS)

__global__ void prep_kernel(const float* __restrict__ x,
                            const float* __restrict__ ln_g,
                            const float* __restrict__ ln_b,
                            const float* __restrict__ W_in,
                            const float* __restrict__ W_out,
                            const float* __restrict__ WB,
                            const float* __restrict__ WC) {
    __shared__ float ss[8], sq[8];
    __shared__ float smu, srstd;
    int blk = blockIdx.x;
    int tid = threadIdx.x;

    if (blk < PREP_WIN_BLKS) {
        int i = blk * 256 + tid;
        float4 v = ((const float4*)W_in)[i];
        ((__half2*)g_WinH)[i * 2]     = __floats2half2_rn(v.x, v.y);
        ((__half2*)g_WinH)[i * 2 + 1] = __floats2half2_rn(v.z, v.w);
        return;
    }
    blk -= PREP_WIN_BLKS;
    if (blk < PREP_WOUT_BLKS) {
        int i = blk * 256 + tid;
        float4 v = ((const float4*)W_out)[i];
        ((__half2*)g_WoutH)[i * 2]     = __floats2half2_rn(v.x, v.y);
        ((__half2*)g_WoutH)[i * 2 + 1] = __floats2half2_rn(v.z, v.w);
        return;
    }
    blk -= PREP_WOUT_BLKS;
    if (blk < PREP_WBC_BLKS) {
        int i = blk * 256 + tid;
        int k = i >> 5, o = i & 31;
        float v = (o < 16) ? WB[k * DS + o] : WC[k * DS + (o - 16)];
        g_WBC[i] = __float2half(v);
        return;
    }
    blk -= PREP_WBC_BLKS;
    {
        int row = blk;
        const float4* xr = (const float4*)(x + (size_t)row * DM);
        float4 v = xr[tid];
        float s = v.x + v.y + v.z + v.w;
        float q = v.x * v.x + v.y * v.y + v.z * v.z + v.w * v.w;
        #pragma unroll
        for (int o = 16; o; o >>= 1) {
            s += __shfl_down_sync(0xFFFFFFFFu, s, o);
            q += __shfl_down_sync(0xFFFFFFFFu, q, o);
        }
        int w = tid >> 5, l = tid & 31;
        if (l == 0) { ss[w] = s; sq[w] = q; }
        __syncthreads();
        if (tid == 0) {
            float S = 0.f, Q = 0.f;
            #pragma unroll
            for (int i = 0; i < 8; i++) { S += ss[i]; Q += sq[i]; }
            float mu = S * (1.0f / DM);
            float var = Q * (1.0f / DM) - mu * mu;
            smu = mu; srstd = rsqrtf(var + 1e-5f);
        }
        __syncthreads();
        float mu = smu, rstd = srstd;
        float4 gv = ((const float4*)ln_g)[tid];
        float4 bv = ((const float4*)ln_b)[tid];
        __half2* orow = (__half2*)(g_xnh + (size_t)row * DM);
        orow[tid * 2]     = __floats2half2_rn((v.x - mu) * rstd * gv.x + bv.x,
                                              (v.y - mu) * rstd * gv.y + bv.y);
        orow[tid * 2 + 1] = __floats2half2_rn((v.z - mu) * rstd * gv.z + bv.z,
                                              (v.w - mu) * rstd * gv.w + bv.w);
    }
}

// ---------------- fp16 mma GEMM, 4-stage, hoisted frags, no bottom sync ----------------
// MODE 0: C = A@B + bias.  MODE 2: split-K2 partial, no bias, fp32 out.
#define GA_ST 80
#define GA_BYTES (128 * GA_ST)
#define GB_ST 272
#define GB_BYTES (32 * GB_ST)
#define GSTAGE (GA_BYTES + GB_BYTES)
#define GSM (4 * GSTAGE)

template <int MODE, typename OutT>
__global__ __launch_bounds__(256, 2) void gemm_f16(
    const __half* __restrict__ Amat, const __half* __restrict__ Bmat,
    const float* __restrict__ bias,
    OutT* __restrict__ Cmat, int M, int N, int K)
{
    extern __shared__ char sm[];
    uint32_t sb = smem_u32(sm);
    int tid = threadIdx.x;
    int wid = tid >> 5, lane = tid & 31;
    int wm = wid >> 2, wn = wid & 3;
    int gid = lane >> 2, tig = lane & 3;
    int mBase = blockIdx.y * 128, nBase = blockIdx.x * 128;
    int kOff = (MODE == 2) ? blockIdx.z * (K / 2) : 0;
    const int S = (MODE == 2) ? (K / 2) / 32 : K / 32;
    OutT* Cout = (MODE == 2) ? Cmat + (size_t)blockIdx.z * M * N : Cmat;

    float acc[4][4][4];
    #pragma unroll
    for (int i = 0; i < 4; i++)
        #pragma unroll
        for (int j = 0; j < 4; j++)
            #pragma unroll
            for (int c = 0; c < 4; c++) acc[i][j][c] = 0.f;

    auto stage_load = [&](int buf, int k0) {
        uint32_t ab = sb + buf * GSTAGE;
        uint32_t bb = ab + GA_BYTES;
        #pragma unroll
        for (int q = 0; q < 2; q++) {
            int lin = tid + q * 256;
            int row = lin >> 2, ch = lin & 3;
            cp16(ab + row * GA_ST + ch * 16,
                 Amat + (size_t)(mBase + row) * K + k0 + ch * 8);
        }
        #pragma unroll
        for (int q = 0; q < 2; q++) {
            int lin = tid + q * 256;
            int row = lin >> 4, ch = lin & 15;
            cp16(bb + row * GB_ST + ch * 16,
                 Bmat + (size_t)(k0 + row) * N + nBase + ch * 8);
        }
        asm volatile("cp.async.commit_group;" ::: "memory");
    };

    stage_load(0, kOff);
    stage_load(1, kOff + 32);
    stage_load(2, kOff + 64);
    for (int s = 0; s < S; s++) {
        asm volatile("cp.async.wait_group 2;" ::: "memory");
        __syncthreads();
        if (s + 3 < S) stage_load((s + 3) & 3, kOff + (s + 3) * 32);
        else           asm volatile("cp.async.commit_group;" ::: "memory");

        uint32_t ab = sb + (s & 3) * GSTAGE;
        uint32_t bb = ab + GA_BYTES;
        uint32_t af[2][4][4], bf[2][2][4];
        #pragma unroll
        for (int k16 = 0; k16 < 2; k16++) {
            #pragma unroll
            for (int mt = 0; mt < 4; mt++) {
                uint32_t addr = ab + (wm * 64 + mt * 16 + (lane & 15)) * GA_ST
                              + k16 * 32 + ((lane >> 4) << 4);
                ldsm4(af[k16][mt], addr);
            }
            #pragma unroll
            for (int bt = 0; bt < 2; bt++) {
                uint32_t addr = bb + (k16 * 16 + (lane & 15)) * GB_ST
                              + (wn * 32 + bt * 16 + ((lane >> 4) << 3)) * 2;
                ldsm4t(bf[k16][bt], addr);
            }
        }
        #pragma unroll
        for (int k16 = 0; k16 < 2; k16++)
            #pragma unroll
            for (int mt = 0; mt < 4; mt++)
                #pragma unroll
                for (int nt = 0; nt < 4; nt++)
                    mma_f16(acc[mt][nt], af[k16][mt], &bf[k16][nt >> 1][(nt & 1) * 2]);
        // no bottom sync: with 4 buffers, iter s+1's stage_load writes buf (s+4)&3,
        // touched only after that iter's top __syncthreads.
    }

    #pragma unroll
    for (int mt = 0; mt < 4; mt++) {
        int r0 = mBase + wm * 64 + mt * 16 + gid;
        #pragma unroll
        for (int nt = 0; nt < 4; nt++) {
            int cN = nBase + wn * 32 + nt * 8 + tig * 2;
            float o0x = acc[mt][nt][0], o0y = acc[mt][nt][1];
            float o1x = acc[mt][nt][2], o1y = acc[mt][nt][3];
            if (MODE == 0) {
                float2 bv = *(const float2*)(bias + cN);
                o0x += bv.x; o0y += bv.y;
                o1x += bv.x; o1y += bv.y;
            }
            if (sizeof(OutT) == 2) {
                *(__half2*)((__half*)Cout + (size_t)r0 * N + cN)       = __floats2half2_rn(o0x, o0y);
                *(__half2*)((__half*)Cout + (size_t)(r0 + 8) * N + cN) = __floats2half2_rn(o1x, o1y);
            } else {
                *(float2*)((float*)Cout + (size_t)r0 * N + cN)       = make_float2(o0x, o0y);
                *(float2*)((float*)Cout + (size_t)(r0 + 8) * N + cN) = make_float2(o1x, o1y);
            }
        }
    }
}

// ---------------- gemm2 split-K reduce: out = p0 + p1 + bias + x ----------------
__global__ void g2_reduce_kernel(const float* __restrict__ bias,
                                 const float* __restrict__ x,
                                 float* __restrict__ out) {
    int i = blockIdx.x * 256 + threadIdx.x;
    float4 p0 = ((const float4*)g_G2p[0])[i];
    float4 p1 = ((const float4*)g_G2p[1])[i];
    float4 bv = ((const float4*)bias)[i & (DM / 4 - 1)];
    float4 xv = ((const float4*)x)[i];
    float4 o;
    o.x = p0.x + p1.x + bv.x + xv.x;
    o.y = p0.y + p1.y + bv.y + xv.y;
    o.z = p0.z + p1.z + bv.z + xv.z;
    o.w = p0.w + p1.w + bv.w + xv.w;
    ((float4*)out)[i] = o;
}

// ---------------- 3. depthwise causal conv1d + silu (half2, 2 ch/thread) ----------------
__global__ void conv_silu_kernel(const float* __restrict__ cw,
                                 const float* __restrict__ cb) {
    int i = blockIdx.x * 256 + threadIdx.x;     // over TOK*DI/2
    int d2  = i & (DI / 2 - 1);
    int d   = d2 * 2;
    int tok = i >> 10;
    int t   = tok & (T_ - 1);
    float4 w0 = *(const float4*)(cw + d * 4);
    float4 w1 = *(const float4*)(cw + d * 4 + 4);
    float2 cbv = *(const float2*)(cb + d);
    const __half* base = g_projh + (size_t)tok * (2 * DI) + d;
    float a0 = cbv.x, a1 = cbv.y;
    if (t >= 3) { float2 f = __half22float2(*(const __half2*)(base - 3 * 2 * DI));
                  a0 = fmaf(w0.x, f.x, a0); a1 = fmaf(w1.x, f.y, a1); }
    if (t >= 2) { float2 f = __half22float2(*(const __half2*)(base - 2 * 2 * DI));
                  a0 = fmaf(w0.y, f.x, a0); a1 = fmaf(w1.y, f.y, a1); }
    if (t >= 1) { float2 f = __half22float2(*(const __half2*)(base - 1 * 2 * DI));
                  a0 = fmaf(w0.z, f.x, a0); a1 = fmaf(w1.z, f.y, a1); }
    { float2 f = __half22float2(*(const __half2*)(base));
      a0 = fmaf(w0.w, f.x, a0); a1 = fmaf(w1.w, f.y, a1); }
    *(__half2*)(g_xch + (size_t)tok * DI + d) = __floats2half2_rn(siluf_(a0), siluf_(a1));
}

// ---------------- 4. B_t / C_t: fp16 mma split-K GEMM (partials only) ----------------
#define CA_BYTES (128 * 80)
#define CB_BYTES (32 * 80)
#define CSTAGE (CA_BYTES + CB_BYTES)
#define CSM (3 * CSTAGE)

__global__ __launch_bounds__(256) void bc_mma_kernel() {
    extern __shared__ char sm[];
    uint32_t sb = smem_u32(sm);
    int tid = threadIdx.x;
    int wid = tid >> 5, lane = tid & 31;
    int wm = wid >> 1, wn = wid & 1;
    int gid = lane >> 2, tig = lane & 3;
    int tok0 = blockIdx.x * 128;
    int kBase = blockIdx.y * (DI / KSL);
    const __half* X = g_xch;
    const __half* W = g_WBC;

    float acc[2][2][4];
    #pragma unroll
    for (int i = 0; i < 2; i++)
        #pragma unroll
        for (int j = 0; j < 2; j++)
            #pragma unroll
            for (int c = 0; c < 4; c++) acc[i][j][c] = 0.f;

    auto stage_load = [&](int buf, int k0) {
        uint32_t ab = sb + buf * CSTAGE;
        uint32_t bb = ab + CA_BYTES;
        #pragma unroll
        for (int q = 0; q < 2; q++) {
            int lin = tid + q * 256;
            int row = lin >> 2, ch = lin & 3;
            cp16(ab + row * 80 + ch * 16,
                 X + (size_t)(tok0 + row) * DI + kBase + k0 + ch * 8);
        }
        if (tid < 128) {
            int row = tid >> 2, ch = tid & 3;
            cp16(bb + row * 80 + ch * 16,
                 W + (size_t)(kBase + k0 + row) * 32 + ch * 8);
        }
        asm volatile("cp.async.commit_group;" ::: "memory");
    };

    const int S = (DI / KSL) / 32;
    stage_load(0, 0);
    stage_load(1, 32);
    for (int s = 0; s < S; s++) {
        asm volatile("cp.async.wait_group 1;" ::: "memory");
        __syncthreads();
        if (s + 2 < S) stage_load((s + 2) % 3, (s + 2) * 32);

        uint32_t ab = sb + (s % 3) * CSTAGE;
        uint32_t bb = ab + CA_BYTES;
        uint32_t af[2][2][4], bf[2][4];
        #pragma unroll
        for (int k16 = 0; k16 < 2; k16++) {
            #pragma unroll
            for (int mt = 0; mt < 2; mt++) {
                uint32_t addr = ab + (wm * 32 + mt * 16 + (lane & 15)) * 80
                              + k16 * 32 + ((lane >> 4) << 4);
                ldsm4(af[k16][mt], addr);
            }
            {
                uint32_t addr = bb + (k16 * 16 + (lane & 15)) * 80
                              + (wn * 16 + ((lane >> 4) << 3)) * 2;
                ldsm4t(bf[k16], addr);
            }
        }
        #pragma unroll
        for (int k16 = 0; k16 < 2; k16++)
            #pragma unroll
            for (int mt = 0; mt < 2; mt++)
                #pragma unroll
                for (int nt = 0; nt < 2; nt++)
                    mma_f16(acc[mt][nt], af[k16][mt], &bf[k16][nt * 2]);
    }

    #pragma unroll
    for (int mt = 0; mt < 2; mt++) {
        int r0 = tok0 + wm * 32 + mt * 16 + gid;
        #pragma unroll
        for (int nt = 0; nt < 2; nt++) {
            int o = wn * 16 + nt * 8 + tig * 2;
            *(float2*)&g_BCp[blockIdx.y][r0][o]     = make_float2(acc[mt][nt][0], acc[mt][nt][1]);
            *(float2*)&g_BCp[blockIdx.y][r0 + 8][o] = make_float2(acc[mt][nt][2], acc[mt][nt][3]);
        }
    }
}

__global__ void bc_reduce_kernel(const float* __restrict__ bB,
                                 const float* __restrict__ bC) {
    int idx = blockIdx.x * 256 + threadIdx.x;
    int o = idx & 31, tok = idx >> 5;
    float s = 0.f;
    #pragma unroll
    for (int p = 0; p < KSL; p++) s += g_BCp[p][tok][o];
    if (o < 16) g_Bt[tok * DS + o]        = s + bB[o];
    else        g_Ct[tok * DS + (o - 16)] = s + bC[o - 16];
}

// ---------------- 5. scan pass 1 ----------------
__global__ void scan1_kernel(const float* __restrict__ A) {
    __shared__ float sB[CHL][DS];
    int tid = threadIdx.x;
    int d  = blockIdx.x * 128 + tid;
    int ch = blockIdx.y, bb = blockIdx.z;
    int tok0 = bb * T_ + ch * CHL;
    float* sBf = &sB[0][0];
    #pragma unroll
    for (int q = 0; q < (CHL * DS) / 128; q++)
        sBf[tid + q * 128] = g_Bt[tok0 * DS + tid + q * 128];
    float a[DS], h[DS];
    #pragma unroll
    for (int s = 0; s < DS; s++) {
        a[s] = sigmoidf_(A[d * DS + s]);
        h[s] = 0.f;
    }
    __syncthreads();
    for (int t = 0; t < CHL; t++) {
        float x = __half2float(g_xch[(size_t)(tok0 + t) * DI + d]);
        #pragma unroll
        for (int s = 0; s < DS; s++)
            h[s] = fmaf(a[s], h[s], sB[t][s] * x);
    }
    float* ep = g_E + ((size_t)(bb * NCH + ch) * DI + d) * DS;
    #pragma unroll
    for (int s = 0; s < DS; s++) ep[s] = h[s];
}

// ---------------- 6. serial carry ----------------
__global__ void carry_kernel(const float* __restrict__ A) {
    int idx = blockIdx.x * 256 + threadIdx.x;
    int d = idx & (DI - 1), bb = idx >> 11;
    float aL[DS], st[DS];
    #pragma unroll
    for (int s = 0; s < DS; s++) {
        float a = sigmoidf_(A[d * DS + s]);
        #pragma unroll
        for (int r = 0; r < 5; r++) a *= a;   // a^32
        aL[s] = a;
        st[s] = 0.f;
    }
    for (int c = 0; c < NCH; c++) {
        float* sp = g_S + ((size_t)(bb * NCH + c) * DI + d) * DS;
        const float* ep = g_E + ((size_t)(bb * NCH + c) * DI + d) * DS;
        #pragma unroll
        for (int s = 0; s < DS; s++) sp[s] = st[s];
        #pragma unroll
        for (int s = 0; s < DS; s++) st[s] = fmaf(aL[s], st[s], ep[s]);
    }
}

// ---------------- 7. scan pass 2 + gate epilogue ----------------
__global__ void scan2_kernel(const float* __restrict__ A,
                             const float* __restrict__ Dv) {
    __shared__ float sB[CHL][DS], sC[CHL][DS];
    int tid = threadIdx.x;
    int d  = blockIdx.x * 128 + tid;
    int ch = blockIdx.y, bb = blockIdx.z;
    int tok0 = bb * T_ + ch * CHL;
    #pragma unroll
    for (int q = 0; q < (CHL * DS) / 128; q++) {
        (&sB[0][0])[tid + q * 128] = g_Bt[tok0 * DS + tid + q * 128];
        (&sC[0][0])[tid + q * 128] = g_Ct[tok0 * DS + tid + q * 128];
    }
    const float* sp = g_S + ((size_t)(bb * NCH + ch) * DI + d) * DS;
    float a[DS], h[DS];
    #pragma unroll
    for (int s = 0; s < DS; s++) {
        a[s] = sigmoidf_(A[d * DS + s]);
        h[s] = sp[s];
    }
    float Dd = Dv[d];
    __syncthreads();
    for (int t = 0; t < CHL; t++) {
        int tok = tok0 + t;
        float x = __half2float(g_xch[(size_t)tok * DI + d]);
        float yv = Dd * x;
        #pragma unroll
        for (int s = 0; s < DS; s++) {
            h[s] = fmaf(a[s], h[s], sB[t][s] * x);
            yv = fmaf(h[s], sC[t][s], yv);
        }
        float gt = __half2float(g_projh[(size_t)tok * (2 * DI) + DI + d]);
        g_y[(size_t)tok * DI + d] = __float2half(yv * siluf_(gt));
    }
}

// ---------------- launch ----------------
extern "C" void kernel_launch(void* const* d_in, const int* in_sizes, int n_in,
                              void* d_out, int out_size) {
    const float* x      = (const float*)d_in[0];
    const float* ln_g   = (const float*)d_in[1];
    const float* ln_b   = (const float*)d_in[2];
    const float* W_in   = (const float*)d_in[3];
    const float* b_in   = (const float*)d_in[4];
    const float* conv_w = (const float*)d_in[5];
    const float* conv_b = (const float*)d_in[6];
    const float* A      = (const float*)d_in[7];
    const float* W_B    = (const float*)d_in[8];
    const float* b_B    = (const float*)d_in[9];
    const float* W_C    = (const float*)d_in[10];
    const float* b_C    = (const float*)d_in[11];
    const float* Dv     = (const float*)d_in[12];
    const float* W_out  = (const float*)d_in[13];
    const float* b_out  = (const float*)d_in[14];
    float* out = (float*)d_out;

    void *pxnh, *pprojh, *py, *pwih, *pwoh, *pg2p;
    cudaGetSymbolAddress(&pxnh,  g_xnh);
    cudaGetSymbolAddress(&pprojh, g_projh);
    cudaGetSymbolAddress(&py,    g_y);
    cudaGetSymbolAddress(&pwih,  g_WinH);
    cudaGetSymbolAddress(&pwoh,  g_WoutH);
    cudaGetSymbolAddress(&pg2p,  g_G2p);

    cudaFuncSetAttribute((const void*)gemm_f16<0, __half>,
                         cudaFuncAttributeMaxDynamicSharedMemorySize, GSM);
    cudaFuncSetAttribute((const void*)gemm_f16<2, float>,
                         cudaFuncAttributeMaxDynamicSharedMemorySize, GSM);
    cudaFuncSetAttribute((const void*)bc_mma_kernel,
                         cudaFuncAttributeMaxDynamicSharedMemorySize, CSM);

    // 1. fused prep
    prep_kernel<<<PREP_BLKS, 256>>>(x, ln_g, ln_b, W_in, W_out, W_B, W_C);

    // 2. proj = xn @ W_in + b_in   (M=2048, N=4096, K=1024)
    gemm_f16<0, __half><<<dim3((2 * DI) / 128, TOK / 128), 256, GSM>>>(
        (const __half*)pxnh, (const __half*)pwih, b_in,
        (__half*)pprojh, TOK, 2 * DI, DM);

    // 3.
    conv_silu_kernel<<<(TOK * DI) / 512, 256>>>(conv_w, conv_b);

    // 4-5. bc partials + reduce
    bc_mma_kernel<<<dim3(TOK / 128, KSL), 256, CSM>>>();
    bc_reduce_kernel<<<(TOK * 32) / 256, 256>>>(b_B, b_C);

    // 6-8. scans
    scan1_kernel<<<dim3(DI / 128, NCH, B_), 128>>>(A);
    carry_kernel<<<(B_ * DI) / 256, 256>>>(A);
    scan2_kernel<<<dim3(DI / 128, NCH, B_), 128>>>(A, Dv);

    // 9-10. gemm2 split-K2 partials + reduce -> out
    gemm_f16<2, float><<<dim3(DM / 128, TOK / 128, 2), 256, GSM>>>(
        (const __half*)py, (const __half*)pwoh, b_out,
        (float*)pg2p, TOK, DM, DI);
    g2_reduce_kernel<<<(TOK * DM) / 1024, 256>>>(b_out, x, out);
}

// round 16
// speedup vs baseline: 1.5235x; 1.4620x over previous
#include <cuda_runtime.h>
#include <cuda_fp16.h>
#include <cstdint>

// ---------------- problem constants ----------------
#define B_   2
#define T_   1024
#define DM   1024      // d_model
#define DI   2048      // d_inner
#define DS   16        // d_state
#define TOK  (B_ * T_) // 2048 tokens
#define NCH  32        // scan chunks
#define CHL  32        // chunk length
#define KSL  8         // bc split-K slices

// ---------------- scratch (static device memory) ----------------
__device__ __half g_xnh  [TOK * DM];
__device__ __half g_WinH [DM * 2 * DI];
__device__ __half g_WoutH[DI * DM];
__device__ __half g_WBC  [DI * 32];
__device__ __half g_projh[TOK * 2 * DI];
__device__ __half g_xch  [TOK * DI];
__device__ float  g_E    [B_ * NCH * DS * DI];   // [b][ch][s][d] (d fastest)
__device__ float  g_S    [B_ * NCH * DS * DI];   // [b][ch][s][d]
__device__ __half g_y    [TOK * DI];
__device__ float  g_BCp  [KSL][TOK][32];
__device__ float  g_G2p  [2][TOK * DM];

__device__ __forceinline__ float sigmoidf_(float x) { return 1.0f / (1.0f + __expf(-x)); }
__device__ __forceinline__ float siluf_(float x)    { return x / (1.0f + __expf(-x)); }

__device__ __forceinline__ uint32_t smem_u32(const void* p) {
    uint32_t a;
    asm("{ .reg .u64 t; cvta.to.shared.u64 t, %1; cvt.u32.u64 %0, t; }"
        : "=r"(a) : "l"(p));
    return a;
}
__device__ __forceinline__ void cp16(uint32_t dst, const void* src) {
    asm volatile("cp.async.cg.shared.global [%0], [%1], 16;"
                 :: "r"(dst), "l"(src) : "memory");
}
__device__ __forceinline__ void ldsm4(uint32_t* r, uint32_t addr) {
    asm volatile("ldmatrix.sync.aligned.m8n8.x4.shared.b16 {%0,%1,%2,%3}, [%4];"
        : "=r"(r[0]), "=r"(r[1]), "=r"(r[2]), "=r"(r[3]) : "r"(addr));
}
__device__ __forceinline__ void ldsm4t(uint32_t* r, uint32_t addr) {
    asm volatile("ldmatrix.sync.aligned.m8n8.x4.trans.shared.b16 {%0,%1,%2,%3}, [%4];"
        : "=r"(r[0]), "=r"(r[1]), "=r"(r[2]), "=r"(r[3]) : "r"(addr));
}
__device__ __forceinline__ void mma_f16(float* c, const uint32_t* a, const uint32_t* b) {
    asm volatile(
        "mma.sync.aligned.m16n8k16.row.col.f32.f16.f16.f32 "
        "{%0,%1,%2,%3}, {%4,%5,%6,%7}, {%8,%9}, {%0,%1,%2,%3};"
        : "+f"(c[0]), "+f"(c[1]), "+f"(c[2]), "+f"(c[3])
        : "r"(a[0]), "r"(a[1]), "r"(a[2]), "r"(a[3]), "r"(b[0]), "r"(b[1]));
}

// ---------------- 1. fused prep: f2h(W_in) | f2h(W_out) | pack_wbc | LayerNorm ----------------
#define PREP_WIN_BLKS  ((DM * 2 * DI) / 1024)   // 4096
#define PREP_WOUT_BLKS ((DI * DM) / 1024)       // 2048
#define PREP_WBC_BLKS  ((DI * 32) / 256)        // 256
#define PREP_LN_BLKS   TOK                      // 2048
#define PREP_BLKS (PREP_WIN_BLKS + PREP_WOUT_BLKS + PREP_WBC_BLKS + PREP_LN_BLKS)

__global__ void prep_kernel(const float* __restrict__ x,
                            const float* __restrict__ ln_g,
                            const float* __restrict__ ln_b,
                            const float* __restrict__ W_in,
                            const float* __restrict__ W_out,
                            const float* __restrict__ WB,
                            const float* __restrict__ WC) {
    __shared__ float ss[8], sq[8];
    __shared__ float smu, srstd;
    int blk = blockIdx.x;
    int tid = threadIdx.x;

    if (blk < PREP_WIN_BLKS) {
        int i = blk * 256 + tid;
        float4 v = ((const float4*)W_in)[i];
        ((__half2*)g_WinH)[i * 2]     = __floats2half2_rn(v.x, v.y);
        ((__half2*)g_WinH)[i * 2 + 1] = __floats2half2_rn(v.z, v.w);
        return;
    }
    blk -= PREP_WIN_BLKS;
    if (blk < PREP_WOUT_BLKS) {
        int i = blk * 256 + tid;
        float4 v = ((const float4*)W_out)[i];
        ((__half2*)g_WoutH)[i * 2]     = __floats2half2_rn(v.x, v.y);
        ((__half2*)g_WoutH)[i * 2 + 1] = __floats2half2_rn(v.z, v.w);
        return;
    }
    blk -= PREP_WOUT_BLKS;
    if (blk < PREP_WBC_BLKS) {
        int i = blk * 256 + tid;
        int k = i >> 5, o = i & 31;
        float v = (o < 16) ? WB[k * DS + o] : WC[k * DS + (o - 16)];
        g_WBC[i] = __float2half(v);
        return;
    }
    blk -= PREP_WBC_BLKS;
    {
        int row = blk;
        const float4* xr = (const float4*)(x + (size_t)row * DM);
        float4 v = xr[tid];
        float s = v.x + v.y + v.z + v.w;
        float q = v.x * v.x + v.y * v.y + v.z * v.z + v.w * v.w;
        #pragma unroll
        for (int o = 16; o; o >>= 1) {
            s += __shfl_down_sync(0xFFFFFFFFu, s, o);
            q += __shfl_down_sync(0xFFFFFFFFu, q, o);
        }
        int w = tid >> 5, l = tid & 31;
        if (l == 0) { ss[w] = s; sq[w] = q; }
        __syncthreads();
        if (tid == 0) {
            float S = 0.f, Q = 0.f;
            #pragma unroll
            for (int i = 0; i < 8; i++) { S += ss[i]; Q += sq[i]; }
            float mu = S * (1.0f / DM);
            float var = Q * (1.0f / DM) - mu * mu;
            smu = mu; srstd = rsqrtf(var + 1e-5f);
        }
        __syncthreads();
        float mu = smu, rstd = srstd;
        float4 gv = ((const float4*)ln_g)[tid];
        float4 bv = ((const float4*)ln_b)[tid];
        __half2* orow = (__half2*)(g_xnh + (size_t)row * DM);
        orow[tid * 2]     = __floats2half2_rn((v.x - mu) * rstd * gv.x + bv.x,
                                              (v.y - mu) * rstd * gv.y + bv.y);
        orow[tid * 2 + 1] = __floats2half2_rn((v.z - mu) * rstd * gv.z + bv.z,
                                              (v.w - mu) * rstd * gv.w + bv.w);
    }
}

// ---------------- fp16 mma GEMM, 4-stage, hoisted frags, no bottom sync ----------------
// MODE 0: C = A@B + bias.  MODE 2: split-K2 partial, no bias, fp32 out.
#define GA_ST 80
#define GA_BYTES (128 * GA_ST)
#define GB_ST 272
#define GB_BYTES (32 * GB_ST)
#define GSTAGE (GA_BYTES + GB_BYTES)
#define GSM (4 * GSTAGE)

template <int MODE, typename OutT>
__global__ __launch_bounds__(256, 2) void gemm_f16(
    const __half* __restrict__ Amat, const __half* __restrict__ Bmat,
    const float* __restrict__ bias,
    OutT* __restrict__ Cmat, int M, int N, int K)
{
    extern __shared__ char sm[];
    uint32_t sb = smem_u32(sm);
    int tid = threadIdx.x;
    int wid = tid >> 5, lane = tid & 31;
    int wm = wid >> 2, wn = wid & 3;
    int gid = lane >> 2, tig = lane & 3;
    int mBase = blockIdx.y * 128, nBase = blockIdx.x * 128;
    int kOff = (MODE == 2) ? blockIdx.z * (K / 2) : 0;
    const int S = (MODE == 2) ? (K / 2) / 32 : K / 32;
    OutT* Cout = (MODE == 2) ? Cmat + (size_t)blockIdx.z * M * N : Cmat;

    float acc[4][4][4];
    #pragma unroll
    for (int i = 0; i < 4; i++)
        #pragma unroll
        for (int j = 0; j < 4; j++)
            #pragma unroll
            for (int c = 0; c < 4; c++) acc[i][j][c] = 0.f;

    auto stage_load = [&](int buf, int k0) {
        uint32_t ab = sb + buf * GSTAGE;
        uint32_t bb = ab + GA_BYTES;
        #pragma unroll
        for (int q = 0; q < 2; q++) {
            int lin = tid + q * 256;
            int row = lin >> 2, ch = lin & 3;
            cp16(ab + row * GA_ST + ch * 16,
                 Amat + (size_t)(mBase + row) * K + k0 + ch * 8);
        }
        #pragma unroll
        for (int q = 0; q < 2; q++) {
            int lin = tid + q * 256;
            int row = lin >> 4, ch = lin & 15;
            cp16(bb + row * GB_ST + ch * 16,
                 Bmat + (size_t)(k0 + row) * N + nBase + ch * 8);
        }
        asm volatile("cp.async.commit_group;" ::: "memory");
    };

    stage_load(0, kOff);
    stage_load(1, kOff + 32);
    stage_load(2, kOff + 64);
    for (int s = 0; s < S; s++) {
        asm volatile("cp.async.wait_group 2;" ::: "memory");
        __syncthreads();
        if (s + 3 < S) stage_load((s + 3) & 3, kOff + (s + 3) * 32);
        else           asm volatile("cp.async.commit_group;" ::: "memory");

        uint32_t ab = sb + (s & 3) * GSTAGE;
        uint32_t bb = ab + GA_BYTES;
        uint32_t af[2][4][4], bf[2][2][4];
        #pragma unroll
        for (int k16 = 0; k16 < 2; k16++) {
            #pragma unroll
            for (int mt = 0; mt < 4; mt++) {
                uint32_t addr = ab + (wm * 64 + mt * 16 + (lane & 15)) * GA_ST
                              + k16 * 32 + ((lane >> 4) << 4);
                ldsm4(af[k16][mt], addr);
            }
            #pragma unroll
            for (int bt = 0; bt < 2; bt++) {
                uint32_t addr = bb + (k16 * 16 + (lane & 15)) * GB_ST
                              + (wn * 32 + bt * 16 + ((lane >> 4) << 3)) * 2;
                ldsm4t(bf[k16][bt], addr);
            }
        }
        #pragma unroll
        for (int k16 = 0; k16 < 2; k16++)
            #pragma unroll
            for (int mt = 0; mt < 4; mt++)
                #pragma unroll
                for (int nt = 0; nt < 4; nt++)
                    mma_f16(acc[mt][nt], af[k16][mt], &bf[k16][nt >> 1][(nt & 1) * 2]);
    }

    #pragma unroll
    for (int mt = 0; mt < 4; mt++) {
        int r0 = mBase + wm * 64 + mt * 16 + gid;
        #pragma unroll
        for (int nt = 0; nt < 4; nt++) {
            int cN = nBase + wn * 32 + nt * 8 + tig * 2;
            float o0x = acc[mt][nt][0], o0y = acc[mt][nt][1];
            float o1x = acc[mt][nt][2], o1y = acc[mt][nt][3];
            if (MODE == 0) {
                float2 bv = *(const float2*)(bias + cN);
                o0x += bv.x; o0y += bv.y;
                o1x += bv.x; o1y += bv.y;
            }
            if (sizeof(OutT) == 2) {
                *(__half2*)((__half*)Cout + (size_t)r0 * N + cN)       = __floats2half2_rn(o0x, o0y);
                *(__half2*)((__half*)Cout + (size_t)(r0 + 8) * N + cN) = __floats2half2_rn(o1x, o1y);
            } else {
                *(float2*)((float*)Cout + (size_t)r0 * N + cN)       = make_float2(o0x, o0y);
                *(float2*)((float*)Cout + (size_t)(r0 + 8) * N + cN) = make_float2(o1x, o1y);
            }
        }
    }
}

// ---------------- gemm2 split-K reduce: out = p0 + p1 + bias + x ----------------
__global__ void g2_reduce_kernel(const float* __restrict__ bias,
                                 const float* __restrict__ x,
                                 float* __restrict__ out) {
    int i = blockIdx.x * 256 + threadIdx.x;
    float4 p0 = ((const float4*)g_G2p[0])[i];
    float4 p1 = ((const float4*)g_G2p[1])[i];
    float4 bv = ((const float4*)bias)[i & (DM / 4 - 1)];
    float4 xv = ((const float4*)x)[i];
    float4 o;
    o.x = p0.x + p1.x + bv.x + xv.x;
    o.y = p0.y + p1.y + bv.y + xv.y;
    o.z = p0.z + p1.z + bv.z + xv.z;
    o.w = p0.w + p1.w + bv.w + xv.w;
    ((float4*)out)[i] = o;
}

// ---------------- 3. depthwise causal conv1d + silu (half2, 2 ch/thread) ----------------
__global__ void conv_silu_kernel(const float* __restrict__ cw,
                                 const float* __restrict__ cb) {
    int i = blockIdx.x * 256 + threadIdx.x;     // over TOK*DI/2
    int d2  = i & (DI / 2 - 1);
    int d   = d2 * 2;
    int tok = i >> 10;
    int t   = tok & (T_ - 1);
    float4 w0 = *(const float4*)(cw + d * 4);
    float4 w1 = *(const float4*)(cw + d * 4 + 4);
    float2 cbv = *(const float2*)(cb + d);
    const __half* base = g_projh + (size_t)tok * (2 * DI) + d;
    float a0 = cbv.x, a1 = cbv.y;
    if (t >= 3) { float2 f = __half22float2(*(const __half2*)(base - 3 * 2 * DI));
                  a0 = fmaf(w0.x, f.x, a0); a1 = fmaf(w1.x, f.y, a1); }
    if (t >= 2) { float2 f = __half22float2(*(const __half2*)(base - 2 * 2 * DI));
                  a0 = fmaf(w0.y, f.x, a0); a1 = fmaf(w1.y, f.y, a1); }
    if (t >= 1) { float2 f = __half22float2(*(const __half2*)(base - 1 * 2 * DI));
                  a0 = fmaf(w0.z, f.x, a0); a1 = fmaf(w1.z, f.y, a1); }
    { float2 f = __half22float2(*(const __half2*)(base));
      a0 = fmaf(w0.w, f.x, a0); a1 = fmaf(w1.w, f.y, a1); }
    *(__half2*)(g_xch + (size_t)tok * DI + d) = __floats2half2_rn(siluf_(a0), siluf_(a1));
}

// ---------------- 4. B_t / C_t: fp16 mma split-K GEMM (partials only) ----------------
#define CA_BYTES (128 * 80)
#define CB_BYTES (32 * 80)
#define CSTAGE (CA_BYTES + CB_BYTES)
#define CSM (3 * CSTAGE)

__global__ __launch_bounds__(256) void bc_mma_kernel() {
    extern __shared__ char sm[];
    uint32_t sb = smem_u32(sm);
    int tid = threadIdx.x;
    int wid = tid >> 5, lane = tid & 31;
    int wm = wid >> 1, wn = wid & 1;
    int gid = lane >> 2, tig = lane & 3;
    int tok0 = blockIdx.x * 128;
    int kBase = blockIdx.y * (DI / KSL);
    const __half* X = g_xch;
    const __half* W = g_WBC;

    float acc[2][2][4];
    #pragma unroll
    for (int i = 0; i < 2; i++)
        #pragma unroll
        for (int j = 0; j < 2; j++)
            #pragma unroll
            for (int c = 0; c < 4; c++) acc[i][j][c] = 0.f;

    auto stage_load = [&](int buf, int k0) {
        uint32_t ab = sb + buf * CSTAGE;
        uint32_t bb = ab + CA_BYTES;
        #pragma unroll
        for (int q = 0; q < 2; q++) {
            int lin = tid + q * 256;
            int row = lin >> 2, ch = lin & 3;
            cp16(ab + row * 80 + ch * 16,
                 X + (size_t)(tok0 + row) * DI + kBase + k0 + ch * 8);
        }
        if (tid < 128) {
            int row = tid >> 2, ch = tid & 3;
            cp16(bb + row * 80 + ch * 16,
                 W + (size_t)(kBase + k0 + row) * 32 + ch * 8);
        }
        asm volatile("cp.async.commit_group;" ::: "memory");
    };

    const int S = (DI / KSL) / 32;
    stage_load(0, 0);
    stage_load(1, 32);
    for (int s = 0; s < S; s++) {
        asm volatile("cp.async.wait_group 1;" ::: "memory");
        __syncthreads();
        if (s + 2 < S) stage_load((s + 2) % 3, (s + 2) * 32);

        uint32_t ab = sb + (s % 3) * CSTAGE;
        uint32_t bb = ab + CA_BYTES;
        uint32_t af[2][2][4], bf[2][4];
        #pragma unroll
        for (int k16 = 0; k16 < 2; k16++) {
            #pragma unroll
            for (int mt = 0; mt < 2; mt++) {
                uint32_t addr = ab + (wm * 32 + mt * 16 + (lane & 15)) * 80
                              + k16 * 32 + ((lane >> 4) << 4);
                ldsm4(af[k16][mt], addr);
            }
            {
                uint32_t addr = bb + (k16 * 16 + (lane & 15)) * 80
                              + (wn * 16 + ((lane >> 4) << 3)) * 2;
                ldsm4t(bf[k16], addr);
            }
        }
        #pragma unroll
        for (int k16 = 0; k16 < 2; k16++)
            #pragma unroll
            for (int mt = 0; mt < 2; mt++)
                #pragma unroll
                for (int nt = 0; nt < 2; nt++)
                    mma_f16(acc[mt][nt], af[k16][mt], &bf[k16][nt * 2]);
    }

    #pragma unroll
    for (int mt = 0; mt < 2; mt++) {
        int r0 = tok0 + wm * 32 + mt * 16 + gid;
        #pragma unroll
        for (int nt = 0; nt < 2; nt++) {
            int o = wn * 16 + nt * 8 + tig * 2;
            *(float2*)&g_BCp[blockIdx.y][r0][o]     = make_float2(acc[mt][nt][0], acc[mt][nt][1]);
            *(float2*)&g_BCp[blockIdx.y][r0 + 8][o] = make_float2(acc[mt][nt][2], acc[mt][nt][3]);
        }
    }
}

// ---------------- 5. scan pass 1 (computes Bt slice from partials in-block) ----------------
__global__ void scan1_kernel(const float* __restrict__ A,
                             const float* __restrict__ bB) {
    __shared__ float sB[CHL][DS];
    int tid = threadIdx.x;
    int d  = blockIdx.x * 128 + tid;
    int ch = blockIdx.y, bb = blockIdx.z;
    int tok0 = bb * T_ + ch * CHL;

    // Bt slice: 32 tok x 16 states = 512 values, 4 per thread
    #pragma unroll
    for (int e = tid; e < CHL * DS; e += 128) {
        int t = e >> 4, o = e & 15;
        float s = 0.f;
        #pragma unroll
        for (int p = 0; p < KSL; p++) s += g_BCp[p][tok0 + t][o];
        sB[t][o] = s + bB[o];
    }
    float a[DS], h[DS];
    #pragma unroll
    for (int s = 0; s < DS; s++) {
        a[s] = sigmoidf_(A[d * DS + s]);
        h[s] = 0.f;
    }
    __syncthreads();
    for (int t = 0; t < CHL; t++) {
        float x = __half2float(g_xch[(size_t)(tok0 + t) * DI + d]);
        #pragma unroll
        for (int s = 0; s < DS; s++)
            h[s] = fmaf(a[s], h[s], sB[t][s] * x);
    }
    size_t ebase = ((size_t)(bb * NCH + ch) * DS) * DI + d;
    #pragma unroll
    for (int s = 0; s < DS; s++) g_E[ebase + (size_t)s * DI] = h[s];   // coalesced
}

// ---------------- 6. serial carry, (d,s)-parallel, coalesced ----------------
__global__ void carry_kernel(const float* __restrict__ A) {
    int idx = blockIdx.x * 256 + threadIdx.x;    // B_*DS*DI = 65536
    int d  = idx & (DI - 1);
    int s  = (idx >> 11) & (DS - 1);
    int bb = idx >> 15;
    float a = sigmoidf_(A[d * DS + s]);
    #pragma unroll
    for (int r = 0; r < 5; r++) a *= a;          // a^32 (CHL=32)
    float st = 0.f;
    size_t base = ((size_t)(bb * NCH) * DS + s) * DI + d;
    const size_t step = (size_t)NCH ? (size_t)DS * DI : 0;  // per-chunk stride
    for (int c = 0; c < NCH; c++) {
        size_t off = base + (size_t)c * DS * DI;
        g_S[off] = st;
        st = fmaf(a, st, g_E[off]);
    }
}

// ---------------- 7. scan pass 2 + gate epilogue (computes Bt/Ct in-block) ----------------
__global__ void scan2_kernel(const float* __restrict__ A,
                             const float* __restrict__ Dv,
                             const float* __restrict__ bB,
                             const float* __restrict__ bC) {
    __shared__ float sB[CHL][DS], sC[CHL][DS];
    int tid = threadIdx.x;
    int d  = blockIdx.x * 128 + tid;
    int ch = blockIdx.y, bb = blockIdx.z;
    int tok0 = bb * T_ + ch * CHL;

    // Bt+Ct slices: 32 tok x 32 cols = 1024 values, 8 per thread
    #pragma unroll
    for (int e = tid; e < CHL * 32; e += 128) {
        int t = e >> 5, o = e & 31;
        float s = 0.f;
        #pragma unroll
        for (int p = 0; p < KSL; p++) s += g_BCp[p][tok0 + t][o];
        if (o < 16) sB[t][o]      = s + bB[o];
        else        sC[t][o - 16] = s + bC[o - 16];
    }
    size_t sbase = ((size_t)(bb * NCH + ch) * DS) * DI + d;
    float a[DS], h[DS];
    #pragma unroll
    for (int s = 0; s < DS; s++) {
        a[s] = sigmoidf_(A[d * DS + s]);
        h[s] = g_S[sbase + (size_t)s * DI];       // coalesced
    }
    float Dd = Dv[d];
    __syncthreads();
    for (int t = 0; t < CHL; t++) {
        int tok = tok0 + t;
        float x = __half2float(g_xch[(size_t)tok * DI + d]);
        float yv = Dd * x;
        #pragma unroll
        for (int s = 0; s < DS; s++) {
            h[s] = fmaf(a[s], h[s], sB[t][s] * x);
            yv = fmaf(h[s], sC[t][s], yv);
        }
        float gt = __half2float(g_projh[(size_t)tok * (2 * DI) + DI + d]);
        g_y[(size_t)tok * DI + d] = __float2half(yv * siluf_(gt));
    }
}

// ---------------- launch ----------------
extern "C" void kernel_launch(void* const* d_in, const int* in_sizes, int n_in,
                              void* d_out, int out_size) {
    const float* x      = (const float*)d_in[0];
    const float* ln_g   = (const float*)d_in[1];
    const float* ln_b   = (const float*)d_in[2];
    const float* W_in   = (const float*)d_in[3];
    const float* b_in   = (const float*)d_in[4];
    const float* conv_w = (const float*)d_in[5];
    const float* conv_b = (const float*)d_in[6];
    const float* A      = (const float*)d_in[7];
    const float* W_B    = (const float*)d_in[8];
    const float* b_B    = (const float*)d_in[9];
    const float* W_C    = (const float*)d_in[10];
    const float* b_C    = (const float*)d_in[11];
    const float* Dv     = (const float*)d_in[12];
    const float* W_out  = (const float*)d_in[13];
    const float* b_out  = (const float*)d_in[14];
    float* out = (float*)d_out;

    void *pxnh, *pprojh, *py, *pwih, *pwoh, *pg2p;
    cudaGetSymbolAddress(&pxnh,  g_xnh);
    cudaGetSymbolAddress(&pprojh, g_projh);
    cudaGetSymbolAddress(&py,    g_y);
    cudaGetSymbolAddress(&pwih,  g_WinH);
    cudaGetSymbolAddress(&pwoh,  g_WoutH);
    cudaGetSymbolAddress(&pg2p,  g_G2p);

    cudaFuncSetAttribute((const void*)gemm_f16<0, __half>,
                         cudaFuncAttributeMaxDynamicSharedMemorySize, GSM);
    cudaFuncSetAttribute((const void*)gemm_f16<2, float>,
                         cudaFuncAttributeMaxDynamicSharedMemorySize, GSM);
    cudaFuncSetAttribute((const void*)bc_mma_kernel,
                         cudaFuncAttributeMaxDynamicSharedMemorySize, CSM);

    // 1. fused prep
    prep_kernel<<<PREP_BLKS, 256>>>(x, ln_g, ln_b, W_in, W_out, W_B, W_C);

    // 2. proj = xn @ W_in + b_in   (M=2048, N=4096, K=1024)
    gemm_f16<0, __half><<<dim3((2 * DI) / 128, TOK / 128), 256, GSM>>>(
        (const __half*)pxnh, (const __half*)pwih, b_in,
        (__half*)pprojh, TOK, 2 * DI, DM);

    // 3.
    conv_silu_kernel<<<(TOK * DI) / 512, 256>>>(conv_w, conv_b);

    // 4. bc partials (profiled slot)
    bc_mma_kernel<<<dim3(TOK / 128, KSL), 256, CSM>>>();

    // 5-7. scans (bc reduce folded into scan1/scan2)
    scan1_kernel<<<dim3(DI / 128, NCH, B_), 128>>>(A, b_B);
    carry_kernel<<<(B_ * DS * DI) / 256, 256>>>(A);
    scan2_kernel<<<dim3(DI / 128, NCH, B_), 128>>>(A, Dv, b_B, b_C);

    // 8-9. gemm2 split-K2 partials + reduce -> out
    gemm_f16<2, float><<<dim3(DM / 128, TOK / 128, 2), 256, GSM>>>(
        (const __half*)py, (const __half*)pwoh, b_out,
        (float*)pg2p, TOK, DM, DI);
    g2_reduce_kernel<<<(TOK * DM) / 1024, 256>>>(b_out, x, out);
}